// round 12
// baseline (speedup 1.0000x reference)
#include <cuda_runtime.h>
#include <cstdint>

// Problem constants
#define N_IMG 4
#define C_IN  256
#define C_MID 64
#define H     64
#define W     64
#define HW    4096
#define KK    25
#define MASK_STRIDE 116

// Scratch (device globals; no allocation allowed)
__device__ float g_comp[N_IMG * C_MID * HW];            // [n][oc][p]
__device__ float g_mask[N_IMG * HW * MASK_STRIDE];      // [n][p][ij*28+k]
__device__ float g_wenc[C_MID * 9 * 4 * 28];            // [(ic*9+tap)*4+ij][28k]

// Packed fp32x2 helpers (sm_103a; ptxas never auto-fuses these)
__device__ __forceinline__ void fma2(uint64_t& d, uint64_t a, uint64_t b) {
  asm("fma.rn.f32x2 %0, %1, %2, %0;" : "+l"(d) : "l"(a), "l"(b));
}
__device__ __forceinline__ uint64_t bcast2(float v) {
  uint64_t r;
  asm("mov.b64 %0, {%1, %1};" : "=l"(r) : "f"(v));
  return r;
}

// ---------------------------------------------------------------------------
// Kernel 0: one-time transpose of w_enc into k2's smem layout.
// ---------------------------------------------------------------------------
__global__ void transpose_wenc_kernel(const float* __restrict__ w_enc) {
  int i = blockIdx.x * 256 + threadIdx.x;      // over 100*64*9 = 57600
  if (i >= 100 * 64 * 9) return;
  int tap = i % 9;
  int ic  = (i / 9) % 64;
  int e   = i / (9 * 64);
  int k   = e >> 2;
  int ij  = e & 3;
  g_wenc[((ic * 9 + tap) * 4 + ij) * 28 + k] = w_enc[i];
}

// ---------------------------------------------------------------------------
// Kernel 1 (v6, unchanged): 1x1 conv 256 -> 64.
// ---------------------------------------------------------------------------
#define WT_STR 36
#define K1_SMEM ((256 * WT_STR + 32 * 128) * 4)   // 53248 B

__global__ void __launch_bounds__(256) conv1x1_kernel(
    const float* __restrict__ x,
    const float* __restrict__ w_comp,
    const float* __restrict__ b_comp) {
  extern __shared__ float sm1[];
  float* wt = sm1;                  // [256][36]
  float* xs = sm1 + 256 * WT_STR;   // [32][128]

  int tid = threadIdx.x;
  int ocg = tid & 3;
  int pp  = tid >> 2;

  int b     = blockIdx.x;          // 256 blocks
  int oc0   = (b & 1) * 32;
  int gp0   = (b >> 1) * 128;
  int n     = gp0 >> 12;
  int pbase = gp0 & 4095;

  for (int i = tid; i < 256 * 32; i += 256) {
    int j = i >> 8;
    int c = i & 255;
    wt[c * WT_STR + j] = w_comp[(oc0 + j) * 256 + c];
  }

  const float* xb = x + (size_t)n * C_IN * HW + pbase;

  float acc[16];
  #pragma unroll
  for (int j = 0; j < 8; j++) {
    float bv = __ldg(b_comp + oc0 + ocg * 8 + j);
    acc[j] = bv; acc[8 + j] = bv;
  }

  for (int cc = 0; cc < 8; cc++) {
    __syncthreads();
    {
      int c   = tid >> 5;
      int px4 = (tid & 31) * 4;
      #pragma unroll
      for (int i2 = 0; i2 < 4; i2++) {
        int ch = c + i2 * 8;
        float4 v = *(const float4*)(xb + (cc * 32 + ch) * HW + px4);
        *(float4*)(xs + ch * 128 + px4) = v;
      }
    }
    __syncthreads();

    #pragma unroll 8
    for (int c = 0; c < 32; c++) {
      float xv0 = xs[c * 128 + 2 * pp];
      float xv1 = xs[c * 128 + 2 * pp + 1];
      const float4* wr =
          (const float4*)(wt + (cc * 32 + c) * WT_STR + ocg * 8);
      float4 w0 = wr[0], w1 = wr[1];
      acc[0]  += w0.x * xv0;  acc[8]  += w0.x * xv1;
      acc[1]  += w0.y * xv0;  acc[9]  += w0.y * xv1;
      acc[2]  += w0.z * xv0;  acc[10] += w0.z * xv1;
      acc[3]  += w0.w * xv0;  acc[11] += w0.w * xv1;
      acc[4]  += w1.x * xv0;  acc[12] += w1.x * xv1;
      acc[5]  += w1.y * xv0;  acc[13] += w1.y * xv1;
      acc[6]  += w1.z * xv0;  acc[14] += w1.z * xv1;
      acc[7]  += w1.w * xv0;  acc[15] += w1.w * xv1;
    }
  }

  float* ob = g_comp + ((size_t)n * C_MID + oc0 + ocg * 8) * HW + pbase + 2 * pp;
  #pragma unroll
  for (int j = 0; j < 8; j++)
    *(float2*)(ob + j * HW) = make_float2(acc[j], acc[8 + j]);
}

// ---------------------------------------------------------------------------
// Kernel 2 (v5): 3x3 conv + pixel-shuffle softmax, FFMA2 mainloop.
// k-dimension packed in f32x2 pairs: 12 packed accs + 1 scalar per pixel.
// Weights read as b64 pairs via ld.shared.v2.b64 (no packing movs);
// broadcast input packed once per tap. 50 FFMA/tap -> 24 FFMA2 + 2 FFMA.
// ---------------------------------------------------------------------------
#define K2_ICC 16
#define CT_ROW 12
#define WS_FLOATS (K2_ICC * 9 * 4 * 28)      // 16128
#define CT_FLOATS (K2_ICC * 10 * CT_ROW)     // 1920

__global__ void __launch_bounds__(128) conv3x3_softmax_kernel(
    const float* __restrict__ b_enc) {
  extern __shared__ float sm[];
  float* ws = sm;
  float* ct = sm + WS_FLOATS;

  int tid = threadIdx.x;
  int ij  = tid & 3;
  int tp  = tid >> 2;
  int r   = tp >> 2;
  int c0  = (tp & 3) * 2;

  int b  = blockIdx.x;
  int n  = b >> 6;
  int t  = b & 63;
  int h0 = (t >> 3) * 8;
  int w0 = (t & 7) * 8;

  uint64_t ap0[12], ap1[12];          // packed k-pairs (k=2q, 2q+1)
  float a0_24 = 0.f, a1_24 = 0.f;
  #pragma unroll
  for (int q = 0; q < 12; q++) { ap0[q] = 0ull; ap1[q] = 0ull; }

  for (int icc = 0; icc < C_MID / K2_ICC; icc++) {
    int ic0 = icc * K2_ICC;
    {
      const float4* src = (const float4*)(g_wenc + icc * WS_FLOATS);
      float4* dst = (float4*)ws;
      for (int i = tid; i < WS_FLOATS / 4; i += 128) dst[i] = src[i];
    }
    for (int i = tid; i < CT_FLOATS; i += 128) {
      int xx  = i % CT_ROW;
      int yy  = (i / CT_ROW) % 10;
      int icl = i / (10 * CT_ROW);
      int gh = h0 - 1 + yy, gw = w0 - 1 + xx;
      float v = 0.f;
      if (gh >= 0 && gh < H && gw >= 0 && gw < W)
        v = g_comp[((size_t)(n * C_MID + ic0 + icl) << 12) + gh * W + gw];
      ct[(icl * 10 + yy) * CT_ROW + xx] = v;
    }
    __syncthreads();

    for (int icl = 0; icl < K2_ICC; icl++) {
      #pragma unroll
      for (int ty = 0; ty < 3; ty++) {
        #pragma unroll
        for (int tx = 0; tx < 3; tx++) {
          float cv0 = ct[(icl * 10 + r + ty) * CT_ROW + c0 + tx];
          float cv1 = ct[(icl * 10 + r + ty) * CT_ROW + c0 + 1 + tx];
          uint64_t cv0p = bcast2(cv0);
          uint64_t cv1p = bcast2(cv1);
          const float* wb = ws + ((icl * 9 + ty * 3 + tx) * 4 + ij) * 28;
          uint32_t wa = (uint32_t)__cvta_generic_to_shared(wb);
          #pragma unroll
          for (int q = 0; q < 6; q++) {
            uint64_t w01, w23;
            asm("ld.shared.v2.b64 {%0, %1}, [%2];"
                : "=l"(w01), "=l"(w23) : "r"(wa + q * 16));
            fma2(ap0[2*q],   w01, cv0p);
            fma2(ap0[2*q+1], w23, cv0p);
            fma2(ap1[2*q],   w01, cv1p);
            fma2(ap1[2*q+1], w23, cv1p);
          }
          float wl = wb[24];
          a0_24 += wl * cv0;  a1_24 += wl * cv1;
        }
      }
    }
    __syncthreads();
  }

  // unpack to scalars
  float acc0[25], acc1[25];
  #pragma unroll
  for (int q = 0; q < 12; q++) {
    asm("mov.b64 {%0, %1}, %2;" : "=f"(acc0[2*q]), "=f"(acc0[2*q+1]) : "l"(ap0[q]));
    asm("mov.b64 {%0, %1}, %2;" : "=f"(acc1[2*q]), "=f"(acc1[2*q+1]) : "l"(ap1[q]));
  }
  acc0[24] = a0_24;  acc1[24] = a1_24;

  #pragma unroll
  for (int k = 0; k < 25; k++) {
    float bb = __ldg(b_enc + k * 4 + ij);
    acc0[k] += bb; acc1[k] += bb;
  }

  float m0 = acc0[0], m1 = acc1[0];
  #pragma unroll
  for (int k = 1; k < 25; k++) { m0 = fmaxf(m0, acc0[k]); m1 = fmaxf(m1, acc1[k]); }
  float s0 = 0.f, s1 = 0.f;
  #pragma unroll
  for (int k = 0; k < 25; k++) {
    acc0[k] = __expf(acc0[k] - m0); s0 += acc0[k];
    acc1[k] = __expf(acc1[k] - m1); s1 += acc1[k];
  }
  float inv0 = 1.0f / s0, inv1 = 1.0f / s1;

  int p0 = (h0 + r) * W + w0 + c0;
  float* mp0 = g_mask + (size_t)(n * HW + p0) * MASK_STRIDE + ij * 28;
  float* mp1 = mp0 + MASK_STRIDE;
  #pragma unroll
  for (int k = 0; k < 25; k++) {
    mp0[k] = acc0[k] * inv0;
    mp1[k] = acc1[k] * inv1;
  }
}

// ---------------------------------------------------------------------------
// Kernel 3 (v6, unchanged): CARAFE reassembly (R8 config + float4 mask stage).
// ---------------------------------------------------------------------------
#define XS_STRIDE 148

__global__ void __launch_bounds__(256) reassemble_kernel(
    const float* __restrict__ x,
    float* __restrict__ out) {
  __shared__ float ms[64 * MASK_STRIDE];       // 29.7 KB
  __shared__ float xs[2][8 * XS_STRIDE];       // 2 x 4.7 KB

  int tid = threadIdx.x;
  int cg  = tid & 3;
  int pix = tid >> 2;
  int r = pix >> 3, cl = pix & 7;

  int b    = blockIdx.x;          // 1024 blocks
  int cgrp = b & 3;
  int t    = (b >> 2) & 63;
  int n    = b >> 8;
  int h0 = (t >> 3) * 8, w0 = (t & 7) * 8;

  int chl  = tid >> 5;
  int slot = tid & 31;
  int goff[5];
  unsigned lmask = 0, smask = 0;
  #pragma unroll
  for (int q = 0; q < 5; q++) {
    int pos = slot + q * 32;
    int yy = pos / 12, xx = pos - yy * 12;
    int gh = h0 - 2 + yy, gw = w0 - 2 + xx;
    bool in_tile = pos < 144;
    bool v = in_tile && gh >= 0 && gh < H && gw >= 0 && gw < W;
    goff[q] = gh * W + gw;
    if (v) lmask |= (1u << q);
    if (in_tile) smask |= (1u << q);
  }
  int sbase = chl * XS_STRIDE + slot;
  const float* xrow = x + ((size_t)(n * C_IN + cgrp * 64 + chl)) * HW;

  {
    float4* msd = (float4*)ms;
    for (int i = tid; i < 64 * 29; i += 256) {
      int pp  = i / 29;
      int off = i - pp * 29;
      int p = (h0 + (pp >> 3)) * W + w0 + (pp & 7);
      msd[i] = ((const float4*)(g_mask + (size_t)(n * HW + p) * MASK_STRIDE))[off];
    }
  }
  #pragma unroll
  for (int q = 0; q < 5; q++) {
    if (smask >> q & 1) {
      float v = (lmask >> q & 1) ? __ldg(xrow + goff[q]) : 0.f;
      xs[0][sbase + q * 32] = v;
    }
  }
  __syncthreads();

  for (int cc = 0; cc < 8; cc++) {
    if (cc + 1 < 8) {
      const float* xp = xrow + (size_t)(cc + 1) * 8 * HW;
      #pragma unroll
      for (int q = 0; q < 5; q++) {
        if (smask >> q & 1) {
          float v = (lmask >> q & 1) ? __ldg(xp + goff[q]) : 0.f;
          xs[(cc + 1) & 1][sbase + q * 32] = v;
        }
      }
    }

    const float* xbuf = xs[cc & 1];
    #pragma unroll
    for (int s = 0; s < 2; s++) {
      int ch = cg * 2 + s;
      float xw[25];
      #pragma unroll
      for (int dy = 0; dy < 5; dy++)
        #pragma unroll
        for (int dx = 0; dx < 5; dx++)
          xw[dy * 5 + dx] = xbuf[ch * XS_STRIDE + (r + dy) * 12 + cl + dx];

      float res[4];
      #pragma unroll
      for (int ij2 = 0; ij2 < 4; ij2++) {
        const float* mb = ms + pix * MASK_STRIDE + ij2 * 28;
        const float4* mb4 = (const float4*)mb;
        float a = 0.f;
        #pragma unroll
        for (int q = 0; q < 6; q++) {
          float4 m4 = mb4[q];
          a += m4.x * xw[q*4+0] + m4.y * xw[q*4+1]
             + m4.z * xw[q*4+2] + m4.w * xw[q*4+3];
        }
        a += mb[24] * xw[24];
        res[ij2] = a;
      }

      int c_glob = cgrp * 64 + cc * 8 + ch;
      float* ob = out + ((size_t)(n * C_IN + c_glob) * 128 + 2 * (h0 + r)) * 128
                      + 2 * (w0 + cl);
      ((float2*)ob)[0]         = make_float2(res[0], res[1]);
      ((float2*)(ob + 128))[0] = make_float2(res[2], res[3]);
    }
    __syncthreads();
  }
}

// ---------------------------------------------------------------------------
extern "C" void kernel_launch(void* const* d_in, const int* in_sizes, int n_in,
                              void* d_out, int out_size) {
  const float* x      = (const float*)d_in[0];
  const float* w_comp = (const float*)d_in[1];
  const float* b_comp = (const float*)d_in[2];
  const float* w_enc  = (const float*)d_in[3];
  const float* b_enc  = (const float*)d_in[4];
  float* out = (float*)d_out;

  cudaFuncSetAttribute(conv1x1_kernel,
                       cudaFuncAttributeMaxDynamicSharedMemorySize, K1_SMEM);
  cudaFuncSetAttribute(conv3x3_softmax_kernel,
                       cudaFuncAttributeMaxDynamicSharedMemorySize,
                       (WS_FLOATS + CT_FLOATS) * 4);

  transpose_wenc_kernel<<<225, 256>>>(w_enc);
  conv1x1_kernel<<<256, 256, K1_SMEM>>>(x, w_comp, b_comp);
  conv3x3_softmax_kernel<<<256, 128, (WS_FLOATS + CT_FLOATS) * 4>>>(b_enc);
  reassemble_kernel<<<1024, 256>>>(x, out);
}

// round 13
// speedup vs baseline: 1.0160x; 1.0160x over previous
#include <cuda_runtime.h>

// Problem constants
#define N_IMG 4
#define C_IN  256
#define C_MID 64
#define H     64
#define W     64
#define HW    4096
#define KK    25
#define MASK_STRIDE 116

// Scratch (device globals; no allocation allowed)
__device__ float g_comp[N_IMG * C_MID * HW];            // [n][oc][p]
__device__ float g_mask[N_IMG * HW * MASK_STRIDE];      // [n][p][ij*28+k]
__device__ float g_wenc[C_MID * 9 * 4 * 28];            // [(ic*9+tap)*4+ij][28k]

// ---------------------------------------------------------------------------
// Kernel 0: one-time transpose of w_enc into k2's smem layout.
// ---------------------------------------------------------------------------
__global__ void transpose_wenc_kernel(const float* __restrict__ w_enc) {
  int i = blockIdx.x * 256 + threadIdx.x;      // over 100*64*9 = 57600
  if (i >= 100 * 64 * 9) return;
  int tap = i % 9;
  int ic  = (i / 9) % 64;
  int e   = i / (9 * 64);
  int k   = e >> 2;
  int ij  = e & 3;
  g_wenc[((ic * 9 + tap) * 4 + ij) * 28 + k] = w_enc[i];
}

// ---------------------------------------------------------------------------
// Kernel 1 (v6, unchanged): 1x1 conv 256 -> 64.
// ---------------------------------------------------------------------------
#define WT_STR 36
#define K1_SMEM ((256 * WT_STR + 32 * 128) * 4)   // 53248 B

__global__ void __launch_bounds__(256) conv1x1_kernel(
    const float* __restrict__ x,
    const float* __restrict__ w_comp,
    const float* __restrict__ b_comp) {
  extern __shared__ float sm1[];
  float* wt = sm1;                  // [256][36]
  float* xs = sm1 + 256 * WT_STR;   // [32][128]

  int tid = threadIdx.x;
  int ocg = tid & 3;
  int pp  = tid >> 2;

  int b     = blockIdx.x;          // 256 blocks
  int oc0   = (b & 1) * 32;
  int gp0   = (b >> 1) * 128;
  int n     = gp0 >> 12;
  int pbase = gp0 & 4095;

  for (int i = tid; i < 256 * 32; i += 256) {
    int j = i >> 8;
    int c = i & 255;
    wt[c * WT_STR + j] = w_comp[(oc0 + j) * 256 + c];
  }

  const float* xb = x + (size_t)n * C_IN * HW + pbase;

  float acc[16];
  #pragma unroll
  for (int j = 0; j < 8; j++) {
    float bv = __ldg(b_comp + oc0 + ocg * 8 + j);
    acc[j] = bv; acc[8 + j] = bv;
  }

  for (int cc = 0; cc < 8; cc++) {
    __syncthreads();
    {
      int c   = tid >> 5;
      int px4 = (tid & 31) * 4;
      #pragma unroll
      for (int i2 = 0; i2 < 4; i2++) {
        int ch = c + i2 * 8;
        float4 v = *(const float4*)(xb + (cc * 32 + ch) * HW + px4);
        *(float4*)(xs + ch * 128 + px4) = v;
      }
    }
    __syncthreads();

    #pragma unroll 8
    for (int c = 0; c < 32; c++) {
      float xv0 = xs[c * 128 + 2 * pp];
      float xv1 = xs[c * 128 + 2 * pp + 1];
      const float4* wr =
          (const float4*)(wt + (cc * 32 + c) * WT_STR + ocg * 8);
      float4 w0 = wr[0], w1 = wr[1];
      acc[0]  += w0.x * xv0;  acc[8]  += w0.x * xv1;
      acc[1]  += w0.y * xv0;  acc[9]  += w0.y * xv1;
      acc[2]  += w0.z * xv0;  acc[10] += w0.z * xv1;
      acc[3]  += w0.w * xv0;  acc[11] += w0.w * xv1;
      acc[4]  += w1.x * xv0;  acc[12] += w1.x * xv1;
      acc[5]  += w1.y * xv0;  acc[13] += w1.y * xv1;
      acc[6]  += w1.z * xv0;  acc[14] += w1.z * xv1;
      acc[7]  += w1.w * xv0;  acc[15] += w1.w * xv1;
    }
  }

  float* ob = g_comp + ((size_t)n * C_MID + oc0 + ocg * 8) * HW + pbase + 2 * pp;
  #pragma unroll
  for (int j = 0; j < 8; j++)
    *(float2*)(ob + j * HW) = make_float2(acc[j], acc[8 + j]);
}

// ---------------------------------------------------------------------------
// Kernel 2 (v6): 3x3 conv + pixel-shuffle softmax, scalar FFMA (FFMA2
// reverted — measured neutral/negative). K2_ICC 16->8: smem 72KB->36KB,
// 3->5 blocks/SM, 12->20 warps/SM to hide the LDS->FFMA chains.
// ---------------------------------------------------------------------------
#define K2_ICC 8
#define CT_ROW 12
#define WS_FLOATS (K2_ICC * 9 * 4 * 28)      // 8064 (= chunk stride in g_wenc)
#define CT_FLOATS (K2_ICC * 10 * CT_ROW)     // 960

__global__ void __launch_bounds__(128) conv3x3_softmax_kernel(
    const float* __restrict__ b_enc) {
  extern __shared__ float sm[];
  float* ws = sm;               // [icl][tap][ij][28]
  float* ct = sm + WS_FLOATS;   // [icl][yy(10)][xx(12)]

  int tid = threadIdx.x;
  int ij  = tid & 3;
  int tp  = tid >> 2;
  int r   = tp >> 2;
  int c0  = (tp & 3) * 2;

  int b  = blockIdx.x;
  int n  = b >> 6;
  int t  = b & 63;
  int h0 = (t >> 3) * 8;
  int w0 = (t & 7) * 8;

  float acc0[25], acc1[25];
  #pragma unroll
  for (int k = 0; k < 25; k++) { acc0[k] = 0.f; acc1[k] = 0.f; }

  for (int icc = 0; icc < C_MID / K2_ICC; icc++) {
    int ic0 = icc * K2_ICC;
    {
      const float4* src = (const float4*)(g_wenc + icc * WS_FLOATS);
      float4* dst = (float4*)ws;
      for (int i = tid; i < WS_FLOATS / 4; i += 128) dst[i] = src[i];
    }
    for (int i = tid; i < CT_FLOATS; i += 128) {
      int xx  = i % CT_ROW;
      int yy  = (i / CT_ROW) % 10;
      int icl = i / (10 * CT_ROW);
      int gh = h0 - 1 + yy, gw = w0 - 1 + xx;
      float v = 0.f;
      if (gh >= 0 && gh < H && gw >= 0 && gw < W)
        v = g_comp[((size_t)(n * C_MID + ic0 + icl) << 12) + gh * W + gw];
      ct[(icl * 10 + yy) * CT_ROW + xx] = v;
    }
    __syncthreads();

    for (int icl = 0; icl < K2_ICC; icl++) {
      #pragma unroll
      for (int ty = 0; ty < 3; ty++) {
        #pragma unroll
        for (int tx = 0; tx < 3; tx++) {
          float cv0 = ct[(icl * 10 + r + ty) * CT_ROW + c0 + tx];
          float cv1 = ct[(icl * 10 + r + ty) * CT_ROW + c0 + 1 + tx];
          const float* wb = ws + ((icl * 9 + ty * 3 + tx) * 4 + ij) * 28;
          const float4* wb4 = (const float4*)wb;
          #pragma unroll
          for (int q = 0; q < 6; q++) {
            float4 w4 = wb4[q];
            acc0[q*4+0] += w4.x * cv0;  acc1[q*4+0] += w4.x * cv1;
            acc0[q*4+1] += w4.y * cv0;  acc1[q*4+1] += w4.y * cv1;
            acc0[q*4+2] += w4.z * cv0;  acc1[q*4+2] += w4.z * cv1;
            acc0[q*4+3] += w4.w * cv0;  acc1[q*4+3] += w4.w * cv1;
          }
          float wl = wb[24];
          acc0[24] += wl * cv0;  acc1[24] += wl * cv1;
        }
      }
    }
    __syncthreads();
  }

  #pragma unroll
  for (int k = 0; k < 25; k++) {
    float bb = __ldg(b_enc + k * 4 + ij);
    acc0[k] += bb; acc1[k] += bb;
  }

  float m0 = acc0[0], m1 = acc1[0];
  #pragma unroll
  for (int k = 1; k < 25; k++) { m0 = fmaxf(m0, acc0[k]); m1 = fmaxf(m1, acc1[k]); }
  float s0 = 0.f, s1 = 0.f;
  #pragma unroll
  for (int k = 0; k < 25; k++) {
    acc0[k] = __expf(acc0[k] - m0); s0 += acc0[k];
    acc1[k] = __expf(acc1[k] - m1); s1 += acc1[k];
  }
  float inv0 = 1.0f / s0, inv1 = 1.0f / s1;

  int p0 = (h0 + r) * W + w0 + c0;
  float* mp0 = g_mask + (size_t)(n * HW + p0) * MASK_STRIDE + ij * 28;
  float* mp1 = mp0 + MASK_STRIDE;
  #pragma unroll
  for (int k = 0; k < 25; k++) {
    mp0[k] = acc0[k] * inv0;
    mp1[k] = acc1[k] * inv1;
  }
}

// ---------------------------------------------------------------------------
// Kernel 3 (v6, unchanged): CARAFE reassembly (R8 config + float4 mask stage).
// ---------------------------------------------------------------------------
#define XS_STRIDE 148

__global__ void __launch_bounds__(256) reassemble_kernel(
    const float* __restrict__ x,
    float* __restrict__ out) {
  __shared__ float ms[64 * MASK_STRIDE];       // 29.7 KB
  __shared__ float xs[2][8 * XS_STRIDE];       // 2 x 4.7 KB

  int tid = threadIdx.x;
  int cg  = tid & 3;
  int pix = tid >> 2;
  int r = pix >> 3, cl = pix & 7;

  int b    = blockIdx.x;          // 1024 blocks
  int cgrp = b & 3;
  int t    = (b >> 2) & 63;
  int n    = b >> 8;
  int h0 = (t >> 3) * 8, w0 = (t & 7) * 8;

  int chl  = tid >> 5;
  int slot = tid & 31;
  int goff[5];
  unsigned lmask = 0, smask = 0;
  #pragma unroll
  for (int q = 0; q < 5; q++) {
    int pos = slot + q * 32;
    int yy = pos / 12, xx = pos - yy * 12;
    int gh = h0 - 2 + yy, gw = w0 - 2 + xx;
    bool in_tile = pos < 144;
    bool v = in_tile && gh >= 0 && gh < H && gw >= 0 && gw < W;
    goff[q] = gh * W + gw;
    if (v) lmask |= (1u << q);
    if (in_tile) smask |= (1u << q);
  }
  int sbase = chl * XS_STRIDE + slot;
  const float* xrow = x + ((size_t)(n * C_IN + cgrp * 64 + chl)) * HW;

  {
    float4* msd = (float4*)ms;
    for (int i = tid; i < 64 * 29; i += 256) {
      int pp  = i / 29;
      int off = i - pp * 29;
      int p = (h0 + (pp >> 3)) * W + w0 + (pp & 7);
      msd[i] = ((const float4*)(g_mask + (size_t)(n * HW + p) * MASK_STRIDE))[off];
    }
  }
  #pragma unroll
  for (int q = 0; q < 5; q++) {
    if (smask >> q & 1) {
      float v = (lmask >> q & 1) ? __ldg(xrow + goff[q]) : 0.f;
      xs[0][sbase + q * 32] = v;
    }
  }
  __syncthreads();

  for (int cc = 0; cc < 8; cc++) {
    if (cc + 1 < 8) {
      const float* xp = xrow + (size_t)(cc + 1) * 8 * HW;
      #pragma unroll
      for (int q = 0; q < 5; q++) {
        if (smask >> q & 1) {
          float v = (lmask >> q & 1) ? __ldg(xp + goff[q]) : 0.f;
          xs[(cc + 1) & 1][sbase + q * 32] = v;
        }
      }
    }

    const float* xbuf = xs[cc & 1];
    #pragma unroll
    for (int s = 0; s < 2; s++) {
      int ch = cg * 2 + s;
      float xw[25];
      #pragma unroll
      for (int dy = 0; dy < 5; dy++)
        #pragma unroll
        for (int dx = 0; dx < 5; dx++)
          xw[dy * 5 + dx] = xbuf[ch * XS_STRIDE + (r + dy) * 12 + cl + dx];

      float res[4];
      #pragma unroll
      for (int ij2 = 0; ij2 < 4; ij2++) {
        const float* mb = ms + pix * MASK_STRIDE + ij2 * 28;
        const float4* mb4 = (const float4*)mb;
        float a = 0.f;
        #pragma unroll
        for (int q = 0; q < 6; q++) {
          float4 m4 = mb4[q];
          a += m4.x * xw[q*4+0] + m4.y * xw[q*4+1]
             + m4.z * xw[q*4+2] + m4.w * xw[q*4+3];
        }
        a += mb[24] * xw[24];
        res[ij2] = a;
      }

      int c_glob = cgrp * 64 + cc * 8 + ch;
      float* ob = out + ((size_t)(n * C_IN + c_glob) * 128 + 2 * (h0 + r)) * 128
                      + 2 * (w0 + cl);
      ((float2*)ob)[0]         = make_float2(res[0], res[1]);
      ((float2*)(ob + 128))[0] = make_float2(res[2], res[3]);
    }
    __syncthreads();
  }
}

// ---------------------------------------------------------------------------
extern "C" void kernel_launch(void* const* d_in, const int* in_sizes, int n_in,
                              void* d_out, int out_size) {
  const float* x      = (const float*)d_in[0];
  const float* w_comp = (const float*)d_in[1];
  const float* b_comp = (const float*)d_in[2];
  const float* w_enc  = (const float*)d_in[3];
  const float* b_enc  = (const float*)d_in[4];
  float* out = (float*)d_out;

  cudaFuncSetAttribute(conv1x1_kernel,
                       cudaFuncAttributeMaxDynamicSharedMemorySize, K1_SMEM);
  cudaFuncSetAttribute(conv3x3_softmax_kernel,
                       cudaFuncAttributeMaxDynamicSharedMemorySize,
                       (WS_FLOATS + CT_FLOATS) * 4);

  transpose_wenc_kernel<<<225, 256>>>(w_enc);
  conv1x1_kernel<<<256, 256, K1_SMEM>>>(x, w_comp, b_comp);
  conv3x3_softmax_kernel<<<256, 128, (WS_FLOATS + CT_FLOATS) * 4>>>(b_enc);
  reassemble_kernel<<<1024, 256>>>(x, out);
}

// round 14
// speedup vs baseline: 1.0861x; 1.0690x over previous
#include <cuda_runtime.h>

// Problem constants
#define N_IMG 4
#define C_IN  256
#define C_MID 64
#define H     64
#define W     64
#define HW    4096
#define KK    25
#define MASK_STRIDE 116

// Scratch (device globals; no allocation allowed)
__device__ float g_comp[N_IMG * C_MID * HW];            // [n][oc][p]
__device__ float g_mask[N_IMG * HW * MASK_STRIDE];      // [n][p][ij*28+k]
__device__ float g_wenc[C_MID * 9 * 4 * 28];            // [(ic*9+tap)*4+ij][28k]

// ---------------------------------------------------------------------------
// Kernel 0: one-time transpose of w_enc into k2's smem layout.
// ---------------------------------------------------------------------------
__global__ void transpose_wenc_kernel(const float* __restrict__ w_enc) {
  int i = blockIdx.x * 256 + threadIdx.x;      // over 100*64*9 = 57600
  if (i >= 100 * 64 * 9) return;
  int tap = i % 9;
  int ic  = (i / 9) % 64;
  int e   = i / (9 * 64);
  int k   = e >> 2;
  int ij  = e & 3;
  g_wenc[((ic * 9 + tap) * 4 + ij) * 28 + k] = w_enc[i];
}

// ---------------------------------------------------------------------------
// Kernel 1 (v6, unchanged): 1x1 conv 256 -> 64.
// ---------------------------------------------------------------------------
#define WT_STR 36
#define K1_SMEM ((256 * WT_STR + 32 * 128) * 4)   // 53248 B

__global__ void __launch_bounds__(256) conv1x1_kernel(
    const float* __restrict__ x,
    const float* __restrict__ w_comp,
    const float* __restrict__ b_comp) {
  extern __shared__ float sm1[];
  float* wt = sm1;                  // [256][36]
  float* xs = sm1 + 256 * WT_STR;   // [32][128]

  int tid = threadIdx.x;
  int ocg = tid & 3;
  int pp  = tid >> 2;

  int b     = blockIdx.x;          // 256 blocks
  int oc0   = (b & 1) * 32;
  int gp0   = (b >> 1) * 128;
  int n     = gp0 >> 12;
  int pbase = gp0 & 4095;

  for (int i = tid; i < 256 * 32; i += 256) {
    int j = i >> 8;
    int c = i & 255;
    wt[c * WT_STR + j] = w_comp[(oc0 + j) * 256 + c];
  }

  const float* xb = x + (size_t)n * C_IN * HW + pbase;

  float acc[16];
  #pragma unroll
  for (int j = 0; j < 8; j++) {
    float bv = __ldg(b_comp + oc0 + ocg * 8 + j);
    acc[j] = bv; acc[8 + j] = bv;
  }

  for (int cc = 0; cc < 8; cc++) {
    __syncthreads();
    {
      int c   = tid >> 5;
      int px4 = (tid & 31) * 4;
      #pragma unroll
      for (int i2 = 0; i2 < 4; i2++) {
        int ch = c + i2 * 8;
        float4 v = *(const float4*)(xb + (cc * 32 + ch) * HW + px4);
        *(float4*)(xs + ch * 128 + px4) = v;
      }
    }
    __syncthreads();

    #pragma unroll 8
    for (int c = 0; c < 32; c++) {
      float xv0 = xs[c * 128 + 2 * pp];
      float xv1 = xs[c * 128 + 2 * pp + 1];
      const float4* wr =
          (const float4*)(wt + (cc * 32 + c) * WT_STR + ocg * 8);
      float4 w0 = wr[0], w1 = wr[1];
      acc[0]  += w0.x * xv0;  acc[8]  += w0.x * xv1;
      acc[1]  += w0.y * xv0;  acc[9]  += w0.y * xv1;
      acc[2]  += w0.z * xv0;  acc[10] += w0.z * xv1;
      acc[3]  += w0.w * xv0;  acc[11] += w0.w * xv1;
      acc[4]  += w1.x * xv0;  acc[12] += w1.x * xv1;
      acc[5]  += w1.y * xv0;  acc[13] += w1.y * xv1;
      acc[6]  += w1.z * xv0;  acc[14] += w1.z * xv1;
      acc[7]  += w1.w * xv0;  acc[15] += w1.w * xv1;
    }
  }

  float* ob = g_comp + ((size_t)n * C_MID + oc0 + ocg * 8) * HW + pbase + 2 * pp;
  #pragma unroll
  for (int j = 0; j < 8; j++)
    *(float2*)(ob + j * HW) = make_float2(acc[j], acc[8 + j]);
}

// ---------------------------------------------------------------------------
// Kernel 2 (v4 = R11 best config): 3x3 conv + pixel-shuffle softmax.
// ---------------------------------------------------------------------------
#define K2_ICC 16
#define CT_ROW 12
#define WS_FLOATS (K2_ICC * 9 * 4 * 28)      // 16128
#define CT_FLOATS (K2_ICC * 10 * CT_ROW)     // 1920

__global__ void __launch_bounds__(128) conv3x3_softmax_kernel(
    const float* __restrict__ b_enc) {
  extern __shared__ float sm[];
  float* ws = sm;
  float* ct = sm + WS_FLOATS;

  int tid = threadIdx.x;
  int ij  = tid & 3;
  int tp  = tid >> 2;
  int r   = tp >> 2;
  int c0  = (tp & 3) * 2;

  int b  = blockIdx.x;
  int n  = b >> 6;
  int t  = b & 63;
  int h0 = (t >> 3) * 8;
  int w0 = (t & 7) * 8;

  float acc0[25], acc1[25];
  #pragma unroll
  for (int k = 0; k < 25; k++) { acc0[k] = 0.f; acc1[k] = 0.f; }

  for (int icc = 0; icc < C_MID / K2_ICC; icc++) {
    int ic0 = icc * K2_ICC;
    {
      const float4* src = (const float4*)(g_wenc + icc * WS_FLOATS);
      float4* dst = (float4*)ws;
      for (int i = tid; i < WS_FLOATS / 4; i += 128) dst[i] = src[i];
    }
    for (int i = tid; i < CT_FLOATS; i += 128) {
      int xx  = i % CT_ROW;
      int yy  = (i / CT_ROW) % 10;
      int icl = i / (10 * CT_ROW);
      int gh = h0 - 1 + yy, gw = w0 - 1 + xx;
      float v = 0.f;
      if (gh >= 0 && gh < H && gw >= 0 && gw < W)
        v = g_comp[((size_t)(n * C_MID + ic0 + icl) << 12) + gh * W + gw];
      ct[(icl * 10 + yy) * CT_ROW + xx] = v;
    }
    __syncthreads();

    for (int icl = 0; icl < K2_ICC; icl++) {
      #pragma unroll
      for (int ty = 0; ty < 3; ty++) {
        #pragma unroll
        for (int tx = 0; tx < 3; tx++) {
          float cv0 = ct[(icl * 10 + r + ty) * CT_ROW + c0 + tx];
          float cv1 = ct[(icl * 10 + r + ty) * CT_ROW + c0 + 1 + tx];
          const float* wb = ws + ((icl * 9 + ty * 3 + tx) * 4 + ij) * 28;
          const float4* wb4 = (const float4*)wb;
          #pragma unroll
          for (int q = 0; q < 6; q++) {
            float4 w4 = wb4[q];
            acc0[q*4+0] += w4.x * cv0;  acc1[q*4+0] += w4.x * cv1;
            acc0[q*4+1] += w4.y * cv0;  acc1[q*4+1] += w4.y * cv1;
            acc0[q*4+2] += w4.z * cv0;  acc1[q*4+2] += w4.z * cv1;
            acc0[q*4+3] += w4.w * cv0;  acc1[q*4+3] += w4.w * cv1;
          }
          float wl = wb[24];
          acc0[24] += wl * cv0;  acc1[24] += wl * cv1;
        }
      }
    }
    __syncthreads();
  }

  #pragma unroll
  for (int k = 0; k < 25; k++) {
    float bb = __ldg(b_enc + k * 4 + ij);
    acc0[k] += bb; acc1[k] += bb;
  }

  float m0 = acc0[0], m1 = acc1[0];
  #pragma unroll
  for (int k = 1; k < 25; k++) { m0 = fmaxf(m0, acc0[k]); m1 = fmaxf(m1, acc1[k]); }
  float s0 = 0.f, s1 = 0.f;
  #pragma unroll
  for (int k = 0; k < 25; k++) {
    acc0[k] = __expf(acc0[k] - m0); s0 += acc0[k];
    acc1[k] = __expf(acc1[k] - m1); s1 += acc1[k];
  }
  float inv0 = 1.0f / s0, inv1 = 1.0f / s1;

  int p0 = (h0 + r) * W + w0 + c0;
  float* mp0 = g_mask + (size_t)(n * HW + p0) * MASK_STRIDE + ij * 28;
  float* mp1 = mp0 + MASK_STRIDE;
  #pragma unroll
  for (int k = 0; k < 25; k++) {
    mp0[k] = acc0[k] * inv0;
    mp1[k] = acc1[k] * inv1;
  }
}

// ---------------------------------------------------------------------------
// Kernel 3 (v7): CARAFE reassembly, channel-pair mainloop.
// Both channels' 25-word windows held in regs simultaneously; each mask
// float4 LDS now feeds 8 FMAs (both channels) instead of 4 -> per-chunk
// LDS 106 -> 78. launch_bounds(256,2) pins <=128 regs / 2 blocks/SM
// (live-set ~90, should not spill; spill signature = L2% > 30).
// ---------------------------------------------------------------------------
#define XS_STRIDE 148

__global__ void __launch_bounds__(256, 2) reassemble_kernel(
    const float* __restrict__ x,
    float* __restrict__ out) {
  __shared__ float ms[64 * MASK_STRIDE];       // 29.7 KB
  __shared__ float xs[2][8 * XS_STRIDE];       // 2 x 4.7 KB

  int tid = threadIdx.x;
  int cg  = tid & 3;
  int pix = tid >> 2;
  int r = pix >> 3, cl = pix & 7;

  int b    = blockIdx.x;          // 1024 blocks
  int cgrp = b & 3;
  int t    = (b >> 2) & 63;
  int n    = b >> 8;
  int h0 = (t >> 3) * 8, w0 = (t & 7) * 8;

  int chl  = tid >> 5;
  int slot = tid & 31;
  int goff[5];
  unsigned lmask = 0, smask = 0;
  #pragma unroll
  for (int q = 0; q < 5; q++) {
    int pos = slot + q * 32;
    int yy = pos / 12, xx = pos - yy * 12;
    int gh = h0 - 2 + yy, gw = w0 - 2 + xx;
    bool in_tile = pos < 144;
    bool v = in_tile && gh >= 0 && gh < H && gw >= 0 && gw < W;
    goff[q] = gh * W + gw;
    if (v) lmask |= (1u << q);
    if (in_tile) smask |= (1u << q);
  }
  int sbase = chl * XS_STRIDE + slot;
  const float* xrow = x + ((size_t)(n * C_IN + cgrp * 64 + chl)) * HW;

  {
    float4* msd = (float4*)ms;
    for (int i = tid; i < 64 * 29; i += 256) {
      int pp  = i / 29;
      int off = i - pp * 29;
      int p = (h0 + (pp >> 3)) * W + w0 + (pp & 7);
      msd[i] = ((const float4*)(g_mask + (size_t)(n * HW + p) * MASK_STRIDE))[off];
    }
  }
  #pragma unroll
  for (int q = 0; q < 5; q++) {
    if (smask >> q & 1) {
      float v = (lmask >> q & 1) ? __ldg(xrow + goff[q]) : 0.f;
      xs[0][sbase + q * 32] = v;
    }
  }
  __syncthreads();

  for (int cc = 0; cc < 8; cc++) {
    if (cc + 1 < 8) {
      const float* xp = xrow + (size_t)(cc + 1) * 8 * HW;
      #pragma unroll
      for (int q = 0; q < 5; q++) {
        if (smask >> q & 1) {
          float v = (lmask >> q & 1) ? __ldg(xp + goff[q]) : 0.f;
          xs[(cc + 1) & 1][sbase + q * 32] = v;
        }
      }
    }

    const float* xbuf = xs[cc & 1];
    int ch0 = cg * 2;

    // load BOTH channels' 5x5 windows
    float xw0[25], xw1[25];
    #pragma unroll
    for (int dy = 0; dy < 5; dy++)
      #pragma unroll
      for (int dx = 0; dx < 5; dx++) {
        int o = (r + dy) * 12 + cl + dx;
        xw0[dy * 5 + dx] = xbuf[ch0 * XS_STRIDE + o];
        xw1[dy * 5 + dx] = xbuf[(ch0 + 1) * XS_STRIDE + o];
      }

    float res0[4], res1[4];
    #pragma unroll
    for (int ij2 = 0; ij2 < 4; ij2++) {
      const float* mb = ms + pix * MASK_STRIDE + ij2 * 28;
      const float4* mb4 = (const float4*)mb;
      float a0 = 0.f, a1 = 0.f;
      #pragma unroll
      for (int q = 0; q < 6; q++) {
        float4 m4 = mb4[q];
        a0 += m4.x * xw0[q*4+0] + m4.y * xw0[q*4+1]
            + m4.z * xw0[q*4+2] + m4.w * xw0[q*4+3];
        a1 += m4.x * xw1[q*4+0] + m4.y * xw1[q*4+1]
            + m4.z * xw1[q*4+2] + m4.w * xw1[q*4+3];
      }
      float ml = mb[24];
      a0 += ml * xw0[24];
      a1 += ml * xw1[24];
      res0[ij2] = a0;  res1[ij2] = a1;
    }

    int c_glob = cgrp * 64 + cc * 8 + ch0;
    float* ob0 = out + ((size_t)(n * C_IN + c_glob) * 128 + 2 * (h0 + r)) * 128
                     + 2 * (w0 + cl);
    float* ob1 = ob0 + 128 * 128;          // next channel
    ((float2*)ob0)[0]         = make_float2(res0[0], res0[1]);
    ((float2*)(ob0 + 128))[0] = make_float2(res0[2], res0[3]);
    ((float2*)ob1)[0]         = make_float2(res1[0], res1[1]);
    ((float2*)(ob1 + 128))[0] = make_float2(res1[2], res1[3]);

    __syncthreads();
  }
}

// ---------------------------------------------------------------------------
extern "C" void kernel_launch(void* const* d_in, const int* in_sizes, int n_in,
                              void* d_out, int out_size) {
  const float* x      = (const float*)d_in[0];
  const float* w_comp = (const float*)d_in[1];
  const float* b_comp = (const float*)d_in[2];
  const float* w_enc  = (const float*)d_in[3];
  const float* b_enc  = (const float*)d_in[4];
  float* out = (float*)d_out;

  cudaFuncSetAttribute(conv1x1_kernel,
                       cudaFuncAttributeMaxDynamicSharedMemorySize, K1_SMEM);
  cudaFuncSetAttribute(conv3x3_softmax_kernel,
                       cudaFuncAttributeMaxDynamicSharedMemorySize,
                       (WS_FLOATS + CT_FLOATS) * 4);

  transpose_wenc_kernel<<<225, 256>>>(w_enc);
  conv1x1_kernel<<<256, 256, K1_SMEM>>>(x, w_comp, b_comp);
  conv3x3_softmax_kernel<<<256, 128, (WS_FLOATS + CT_FLOATS) * 4>>>(b_enc);
  reassemble_kernel<<<1024, 256>>>(x, out);
}

// round 15
// speedup vs baseline: 1.1104x; 1.0224x over previous
#include <cuda_runtime.h>

// Problem constants
#define N_IMG 4
#define C_IN  256
#define C_MID 64
#define H     64
#define W     64
#define HW    4096
#define KK    25
#define MASK_STRIDE 116

// Scratch (device globals; no allocation allowed)
__device__ float g_comp[N_IMG * C_MID * HW];            // [n][oc][p]
__device__ float g_mask[N_IMG * HW * MASK_STRIDE];      // [n][p][ij*28+k]
__device__ float g_wenc[C_MID * 9 * 4 * 28];            // [(ic*9+tap)*4+ij][28k]

// ---------------------------------------------------------------------------
// Kernel 0: one-time transpose of w_enc into k2's smem layout.
// ---------------------------------------------------------------------------
__global__ void transpose_wenc_kernel(const float* __restrict__ w_enc) {
  int i = blockIdx.x * 256 + threadIdx.x;      // over 100*64*9 = 57600
  if (i >= 100 * 64 * 9) return;
  int tap = i % 9;
  int ic  = (i / 9) % 64;
  int e   = i / (9 * 64);
  int k   = e >> 2;
  int ij  = e & 3;
  g_wenc[((ic * 9 + tap) * 4 + ij) * 28 + k] = w_enc[i];
}

// ---------------------------------------------------------------------------
// Kernel 1 (v6, unchanged): 1x1 conv 256 -> 64.
// ---------------------------------------------------------------------------
#define WT_STR 36
#define K1_SMEM ((256 * WT_STR + 32 * 128) * 4)   // 53248 B

__global__ void __launch_bounds__(256) conv1x1_kernel(
    const float* __restrict__ x,
    const float* __restrict__ w_comp,
    const float* __restrict__ b_comp) {
  extern __shared__ float sm1[];
  float* wt = sm1;                  // [256][36]
  float* xs = sm1 + 256 * WT_STR;   // [32][128]

  int tid = threadIdx.x;
  int ocg = tid & 3;
  int pp  = tid >> 2;

  int b     = blockIdx.x;          // 256 blocks
  int oc0   = (b & 1) * 32;
  int gp0   = (b >> 1) * 128;
  int n     = gp0 >> 12;
  int pbase = gp0 & 4095;

  for (int i = tid; i < 256 * 32; i += 256) {
    int j = i >> 8;
    int c = i & 255;
    wt[c * WT_STR + j] = w_comp[(oc0 + j) * 256 + c];
  }

  const float* xb = x + (size_t)n * C_IN * HW + pbase;

  float acc[16];
  #pragma unroll
  for (int j = 0; j < 8; j++) {
    float bv = __ldg(b_comp + oc0 + ocg * 8 + j);
    acc[j] = bv; acc[8 + j] = bv;
  }

  for (int cc = 0; cc < 8; cc++) {
    __syncthreads();
    {
      int c   = tid >> 5;
      int px4 = (tid & 31) * 4;
      #pragma unroll
      for (int i2 = 0; i2 < 4; i2++) {
        int ch = c + i2 * 8;
        float4 v = *(const float4*)(xb + (cc * 32 + ch) * HW + px4);
        *(float4*)(xs + ch * 128 + px4) = v;
      }
    }
    __syncthreads();

    #pragma unroll 8
    for (int c = 0; c < 32; c++) {
      float xv0 = xs[c * 128 + 2 * pp];
      float xv1 = xs[c * 128 + 2 * pp + 1];
      const float4* wr =
          (const float4*)(wt + (cc * 32 + c) * WT_STR + ocg * 8);
      float4 w0 = wr[0], w1 = wr[1];
      acc[0]  += w0.x * xv0;  acc[8]  += w0.x * xv1;
      acc[1]  += w0.y * xv0;  acc[9]  += w0.y * xv1;
      acc[2]  += w0.z * xv0;  acc[10] += w0.z * xv1;
      acc[3]  += w0.w * xv0;  acc[11] += w0.w * xv1;
      acc[4]  += w1.x * xv0;  acc[12] += w1.x * xv1;
      acc[5]  += w1.y * xv0;  acc[13] += w1.y * xv1;
      acc[6]  += w1.z * xv0;  acc[14] += w1.z * xv1;
      acc[7]  += w1.w * xv0;  acc[15] += w1.w * xv1;
    }
  }

  float* ob = g_comp + ((size_t)n * C_MID + oc0 + ocg * 8) * HW + pbase + 2 * pp;
  #pragma unroll
  for (int j = 0; j < 8; j++)
    *(float2*)(ob + j * HW) = make_float2(acc[j], acc[8 + j]);
}

// ---------------------------------------------------------------------------
// Kernel 2 (v4 = R11 best config, unchanged): 3x3 conv + softmax.
// ---------------------------------------------------------------------------
#define K2_ICC 16
#define CT_ROW 12
#define WS_FLOATS (K2_ICC * 9 * 4 * 28)      // 16128
#define CT_FLOATS (K2_ICC * 10 * CT_ROW)     // 1920

__global__ void __launch_bounds__(128) conv3x3_softmax_kernel(
    const float* __restrict__ b_enc) {
  extern __shared__ float sm[];
  float* ws = sm;
  float* ct = sm + WS_FLOATS;

  int tid = threadIdx.x;
  int ij  = tid & 3;
  int tp  = tid >> 2;
  int r   = tp >> 2;
  int c0  = (tp & 3) * 2;

  int b  = blockIdx.x;
  int n  = b >> 6;
  int t  = b & 63;
  int h0 = (t >> 3) * 8;
  int w0 = (t & 7) * 8;

  float acc0[25], acc1[25];
  #pragma unroll
  for (int k = 0; k < 25; k++) { acc0[k] = 0.f; acc1[k] = 0.f; }

  for (int icc = 0; icc < C_MID / K2_ICC; icc++) {
    int ic0 = icc * K2_ICC;
    {
      const float4* src = (const float4*)(g_wenc + icc * WS_FLOATS);
      float4* dst = (float4*)ws;
      for (int i = tid; i < WS_FLOATS / 4; i += 128) dst[i] = src[i];
    }
    for (int i = tid; i < CT_FLOATS; i += 128) {
      int xx  = i % CT_ROW;
      int yy  = (i / CT_ROW) % 10;
      int icl = i / (10 * CT_ROW);
      int gh = h0 - 1 + yy, gw = w0 - 1 + xx;
      float v = 0.f;
      if (gh >= 0 && gh < H && gw >= 0 && gw < W)
        v = g_comp[((size_t)(n * C_MID + ic0 + icl) << 12) + gh * W + gw];
      ct[(icl * 10 + yy) * CT_ROW + xx] = v;
    }
    __syncthreads();

    for (int icl = 0; icl < K2_ICC; icl++) {
      #pragma unroll
      for (int ty = 0; ty < 3; ty++) {
        #pragma unroll
        for (int tx = 0; tx < 3; tx++) {
          float cv0 = ct[(icl * 10 + r + ty) * CT_ROW + c0 + tx];
          float cv1 = ct[(icl * 10 + r + ty) * CT_ROW + c0 + 1 + tx];
          const float* wb = ws + ((icl * 9 + ty * 3 + tx) * 4 + ij) * 28;
          const float4* wb4 = (const float4*)wb;
          #pragma unroll
          for (int q = 0; q < 6; q++) {
            float4 w4 = wb4[q];
            acc0[q*4+0] += w4.x * cv0;  acc1[q*4+0] += w4.x * cv1;
            acc0[q*4+1] += w4.y * cv0;  acc1[q*4+1] += w4.y * cv1;
            acc0[q*4+2] += w4.z * cv0;  acc1[q*4+2] += w4.z * cv1;
            acc0[q*4+3] += w4.w * cv0;  acc1[q*4+3] += w4.w * cv1;
          }
          float wl = wb[24];
          acc0[24] += wl * cv0;  acc1[24] += wl * cv1;
        }
      }
    }
    __syncthreads();
  }

  #pragma unroll
  for (int k = 0; k < 25; k++) {
    float bb = __ldg(b_enc + k * 4 + ij);
    acc0[k] += bb; acc1[k] += bb;
  }

  float m0 = acc0[0], m1 = acc1[0];
  #pragma unroll
  for (int k = 1; k < 25; k++) { m0 = fmaxf(m0, acc0[k]); m1 = fmaxf(m1, acc1[k]); }
  float s0 = 0.f, s1 = 0.f;
  #pragma unroll
  for (int k = 0; k < 25; k++) {
    acc0[k] = __expf(acc0[k] - m0); s0 += acc0[k];
    acc1[k] = __expf(acc1[k] - m1); s1 += acc1[k];
  }
  float inv0 = 1.0f / s0, inv1 = 1.0f / s1;

  int p0 = (h0 + r) * W + w0 + c0;
  float* mp0 = g_mask + (size_t)(n * HW + p0) * MASK_STRIDE + ij * 28;
  float* mp1 = mp0 + MASK_STRIDE;
  #pragma unroll
  for (int k = 0; k < 25; k++) {
    mp0[k] = acc0[k] * inv0;
    mp1[k] = acc1[k] * inv1;
  }
}

// ---------------------------------------------------------------------------
// Kernel 3 (v8): CARAFE reassembly, channel-pair mainloop.
// vs v7: launch_bounds(256, 2) -> (256, 3). v7 measured 72 regs — the
// 84-reg ceiling implied by 3 blocks/SM fits the proven allocation, so no
// spill expected (watch L2%; spill signature is >30%). 2 -> 3 blocks/SM.
// ---------------------------------------------------------------------------
#define XS_STRIDE 148

__global__ void __launch_bounds__(256, 3) reassemble_kernel(
    const float* __restrict__ x,
    float* __restrict__ out) {
  __shared__ float ms[64 * MASK_STRIDE];       // 29.7 KB
  __shared__ float xs[2][8 * XS_STRIDE];       // 2 x 4.7 KB

  int tid = threadIdx.x;
  int cg  = tid & 3;
  int pix = tid >> 2;
  int r = pix >> 3, cl = pix & 7;

  int b    = blockIdx.x;          // 1024 blocks
  int cgrp = b & 3;
  int t    = (b >> 2) & 63;
  int n    = b >> 8;
  int h0 = (t >> 3) * 8, w0 = (t & 7) * 8;

  int chl  = tid >> 5;
  int slot = tid & 31;
  int goff[5];
  unsigned lmask = 0, smask = 0;
  #pragma unroll
  for (int q = 0; q < 5; q++) {
    int pos = slot + q * 32;
    int yy = pos / 12, xx = pos - yy * 12;
    int gh = h0 - 2 + yy, gw = w0 - 2 + xx;
    bool in_tile = pos < 144;
    bool v = in_tile && gh >= 0 && gh < H && gw >= 0 && gw < W;
    goff[q] = gh * W + gw;
    if (v) lmask |= (1u << q);
    if (in_tile) smask |= (1u << q);
  }
  int sbase = chl * XS_STRIDE + slot;
  const float* xrow = x + ((size_t)(n * C_IN + cgrp * 64 + chl)) * HW;

  {
    float4* msd = (float4*)ms;
    for (int i = tid; i < 64 * 29; i += 256) {
      int pp  = i / 29;
      int off = i - pp * 29;
      int p = (h0 + (pp >> 3)) * W + w0 + (pp & 7);
      msd[i] = ((const float4*)(g_mask + (size_t)(n * HW + p) * MASK_STRIDE))[off];
    }
  }
  #pragma unroll
  for (int q = 0; q < 5; q++) {
    if (smask >> q & 1) {
      float v = (lmask >> q & 1) ? __ldg(xrow + goff[q]) : 0.f;
      xs[0][sbase + q * 32] = v;
    }
  }
  __syncthreads();

  for (int cc = 0; cc < 8; cc++) {
    if (cc + 1 < 8) {
      const float* xp = xrow + (size_t)(cc + 1) * 8 * HW;
      #pragma unroll
      for (int q = 0; q < 5; q++) {
        if (smask >> q & 1) {
          float v = (lmask >> q & 1) ? __ldg(xp + goff[q]) : 0.f;
          xs[(cc + 1) & 1][sbase + q * 32] = v;
        }
      }
    }

    const float* xbuf = xs[cc & 1];
    int ch0 = cg * 2;

    // load BOTH channels' 5x5 windows
    float xw0[25], xw1[25];
    #pragma unroll
    for (int dy = 0; dy < 5; dy++)
      #pragma unroll
      for (int dx = 0; dx < 5; dx++) {
        int o = (r + dy) * 12 + cl + dx;
        xw0[dy * 5 + dx] = xbuf[ch0 * XS_STRIDE + o];
        xw1[dy * 5 + dx] = xbuf[(ch0 + 1) * XS_STRIDE + o];
      }

    float res0[4], res1[4];
    #pragma unroll
    for (int ij2 = 0; ij2 < 4; ij2++) {
      const float* mb = ms + pix * MASK_STRIDE + ij2 * 28;
      const float4* mb4 = (const float4*)mb;
      float a0 = 0.f, a1 = 0.f;
      #pragma unroll
      for (int q = 0; q < 6; q++) {
        float4 m4 = mb4[q];
        a0 += m4.x * xw0[q*4+0] + m4.y * xw0[q*4+1]
            + m4.z * xw0[q*4+2] + m4.w * xw0[q*4+3];
        a1 += m4.x * xw1[q*4+0] + m4.y * xw1[q*4+1]
            + m4.z * xw1[q*4+2] + m4.w * xw1[q*4+3];
      }
      float ml = mb[24];
      a0 += ml * xw0[24];
      a1 += ml * xw1[24];
      res0[ij2] = a0;  res1[ij2] = a1;
    }

    int c_glob = cgrp * 64 + cc * 8 + ch0;
    float* ob0 = out + ((size_t)(n * C_IN + c_glob) * 128 + 2 * (h0 + r)) * 128
                     + 2 * (w0 + cl);
    float* ob1 = ob0 + 128 * 128;          // next channel
    ((float2*)ob0)[0]         = make_float2(res0[0], res0[1]);
    ((float2*)(ob0 + 128))[0] = make_float2(res0[2], res0[3]);
    ((float2*)ob1)[0]         = make_float2(res1[0], res1[1]);
    ((float2*)(ob1 + 128))[0] = make_float2(res1[2], res1[3]);

    __syncthreads();
  }
}

// ---------------------------------------------------------------------------
extern "C" void kernel_launch(void* const* d_in, const int* in_sizes, int n_in,
                              void* d_out, int out_size) {
  const float* x      = (const float*)d_in[0];
  const float* w_comp = (const float*)d_in[1];
  const float* b_comp = (const float*)d_in[2];
  const float* w_enc  = (const float*)d_in[3];
  const float* b_enc  = (const float*)d_in[4];
  float* out = (float*)d_out;

  cudaFuncSetAttribute(conv1x1_kernel,
                       cudaFuncAttributeMaxDynamicSharedMemorySize, K1_SMEM);
  cudaFuncSetAttribute(conv3x3_softmax_kernel,
                       cudaFuncAttributeMaxDynamicSharedMemorySize,
                       (WS_FLOATS + CT_FLOATS) * 4);

  transpose_wenc_kernel<<<225, 256>>>(w_enc);
  conv1x1_kernel<<<256, 256, K1_SMEM>>>(x, w_comp, b_comp);
  conv3x3_softmax_kernel<<<256, 128, (WS_FLOATS + CT_FLOATS) * 4>>>(b_enc);
  reassemble_kernel<<<1024, 256>>>(x, out);
}

// round 16
// speedup vs baseline: 1.1982x; 1.0790x over previous
#include <cuda_runtime.h>
#include <cstdint>

// Problem constants
#define N_IMG 4
#define C_IN  256
#define C_MID 64
#define H     64
#define W     64
#define HW    4096
#define KK    25
#define MASK_STRIDE 116

// Scratch (device globals; no allocation allowed)
__device__ float g_comp[N_IMG * C_MID * HW];            // [n][oc][p]
__device__ float g_mask[N_IMG * HW * MASK_STRIDE];      // [n][p][ij*28+k]
__device__ float g_wB[576 * 104];                       // [kk=ic*9+tap][e pad 104], tf32

// ---------------------------------------------------------------------------
// Kernel 0: one-time build of B matrix for the k2 GEMM.
// g_wB[kk][e] = tf32(w_enc[e][ic][tap]),  e padded 100 -> 104 with zeros.
// ---------------------------------------------------------------------------
__global__ void build_wB_kernel(const float* __restrict__ w_enc) {
  int i = blockIdx.x * 256 + threadIdx.x;      // over 576*104 = 59904
  if (i >= 576 * 104) return;
  int kk = i / 104;
  int e  = i - kk * 104;
  float v = (e < 100) ? w_enc[e * 576 + kk] : 0.f;
  uint32_t tv;
  asm("cvt.rna.tf32.f32 %0, %1;" : "=r"(tv) : "f"(v));
  ((uint32_t*)g_wB)[i] = tv;
}

// ---------------------------------------------------------------------------
// Kernel 1 (v6, unchanged): 1x1 conv 256 -> 64.
// ---------------------------------------------------------------------------
#define WT_STR 36
#define K1_SMEM ((256 * WT_STR + 32 * 128) * 4)   // 53248 B

__global__ void __launch_bounds__(256) conv1x1_kernel(
    const float* __restrict__ x,
    const float* __restrict__ w_comp,
    const float* __restrict__ b_comp) {
  extern __shared__ float sm1[];
  float* wt = sm1;                  // [256][36]
  float* xs = sm1 + 256 * WT_STR;   // [32][128]

  int tid = threadIdx.x;
  int ocg = tid & 3;
  int pp  = tid >> 2;

  int b     = blockIdx.x;          // 256 blocks
  int oc0   = (b & 1) * 32;
  int gp0   = (b >> 1) * 128;
  int n     = gp0 >> 12;
  int pbase = gp0 & 4095;

  for (int i = tid; i < 256 * 32; i += 256) {
    int j = i >> 8;
    int c = i & 255;
    wt[c * WT_STR + j] = w_comp[(oc0 + j) * 256 + c];
  }

  const float* xb = x + (size_t)n * C_IN * HW + pbase;

  float acc[16];
  #pragma unroll
  for (int j = 0; j < 8; j++) {
    float bv = __ldg(b_comp + oc0 + ocg * 8 + j);
    acc[j] = bv; acc[8 + j] = bv;
  }

  for (int cc = 0; cc < 8; cc++) {
    __syncthreads();
    {
      int c   = tid >> 5;
      int px4 = (tid & 31) * 4;
      #pragma unroll
      for (int i2 = 0; i2 < 4; i2++) {
        int ch = c + i2 * 8;
        float4 v = *(const float4*)(xb + (cc * 32 + ch) * HW + px4);
        *(float4*)(xs + ch * 128 + px4) = v;
      }
    }
    __syncthreads();

    #pragma unroll 8
    for (int c = 0; c < 32; c++) {
      float xv0 = xs[c * 128 + 2 * pp];
      float xv1 = xs[c * 128 + 2 * pp + 1];
      const float4* wr =
          (const float4*)(wt + (cc * 32 + c) * WT_STR + ocg * 8);
      float4 w0 = wr[0], w1 = wr[1];
      acc[0]  += w0.x * xv0;  acc[8]  += w0.x * xv1;
      acc[1]  += w0.y * xv0;  acc[9]  += w0.y * xv1;
      acc[2]  += w0.z * xv0;  acc[10] += w0.z * xv1;
      acc[3]  += w0.w * xv0;  acc[11] += w0.w * xv1;
      acc[4]  += w1.x * xv0;  acc[12] += w1.x * xv1;
      acc[5]  += w1.y * xv0;  acc[13] += w1.y * xv1;
      acc[6]  += w1.z * xv0;  acc[14] += w1.z * xv1;
      acc[7]  += w1.w * xv0;  acc[15] += w1.w * xv1;
    }
  }

  float* ob = g_comp + ((size_t)n * C_MID + oc0 + ocg * 8) * HW + pbase + 2 * pp;
  #pragma unroll
  for (int j = 0; j < 8; j++)
    *(float2*)(ob + j * HW) = make_float2(acc[j], acc[8 + j]);
}

// ---------------------------------------------------------------------------
// Kernel 2 (v7 TENSOR): 3x3 conv as tf32 im2col GEMM + softmax.
// Per block: 8x8 px tile. C[64 x 104] = A[64 x 576] * B[576 x 104].
// A gathered from g_comp (halo, zero-pad), K chunked x72. mma.sync
// m16n8k8.tf32 (fallback HMMA on sm_103a). Epilogue: C -> smem logits ->
// register softmax -> g_mask (format unchanged; k3 untouched).
// ---------------------------------------------------------------------------
#define AST 76
#define BST 104
#define LST 108
#define KC  72
#define A_FLOATS (64 * AST)          // 4864
#define B_FLOATS (KC * BST)          // 7488
#define K2_SMEM ((A_FLOATS + B_FLOATS) * 4)   // 49408 B

__global__ void __launch_bounds__(128) conv3x3_softmax_kernel(
    const float* __restrict__ b_enc) {
  extern __shared__ float smK[];
  float* As = smK;                   // [64 px][76]
  float* Bs = smK + A_FLOATS;        // [72 kk][104]

  int tid  = threadIdx.x;
  int lane = tid & 31;
  int wid  = tid >> 5;

  int b  = blockIdx.x;               // 256 blocks
  int n  = b >> 6;
  int t  = b & 63;
  int h0 = (t >> 3) * 8;
  int w0 = (t & 7) * 8;

  float c[13][4];
  #pragma unroll
  for (int nt = 0; nt < 13; nt++)
    #pragma unroll
    for (int q = 0; q < 4; q++) c[nt][q] = 0.f;

  // staging coordinates (fixed per thread): pixel m_st, kk parity kkl0
  int m_st = tid & 63;
  int r_st = m_st >> 3, c_st = m_st & 7;
  int kkl0 = tid >> 6;               // 0 or 1

  // mma fragment bases (fixed per thread)
  int row0 = wid * 16 + (lane >> 2);
  int acol = lane & 3;
  int bn   = lane >> 2;

  const uint32_t* gB = (const uint32_t*)g_wB;
  uint32_t* Asu = (uint32_t*)As;
  uint32_t* Bsu = (uint32_t*)Bs;

  for (int kc = 0; kc < 8; kc++) {
    __syncthreads();
    // stage B chunk (already tf32): linear float4 copy
    {
      const float4* src = (const float4*)(gB + kc * KC * BST);
      float4* dst = (float4*)Bs;
      for (int i = tid; i < B_FLOATS / 4; i += 128) dst[i] = src[i];
    }
    // stage A chunk: im2col gather + tf32 convert
    #pragma unroll 4
    for (int j = 0; j < 36; j++) {
      int kkl = kkl0 + 2 * j;
      int kk  = kc * KC + kkl;
      int ic  = kk / 9;
      int tap = kk - ic * 9;
      int ty  = tap / 3;
      int tx  = tap - ty * 3;
      int gh = h0 + r_st - 1 + ty;
      int gw = w0 + c_st - 1 + tx;
      float v = 0.f;
      if (gh >= 0 && gh < H && gw >= 0 && gw < W)
        v = g_comp[((size_t)(n * C_MID + ic) << 12) + (gh << 6) + gw];
      uint32_t tv;
      asm("cvt.rna.tf32.f32 %0, %1;" : "=r"(tv) : "f"(v));
      Asu[m_st * AST + kkl] = tv;
    }
    __syncthreads();

    // mma phase: warp = one m16 tile; 9 k8-steps x 13 n8-tiles
    #pragma unroll
    for (int k8 = 0; k8 < 9; k8++) {
      int col0 = k8 * 8 + acol;
      uint32_t a0 = Asu[row0 * AST + col0];
      uint32_t a1 = Asu[(row0 + 8) * AST + col0];
      uint32_t a2 = Asu[row0 * AST + col0 + 4];
      uint32_t a3 = Asu[(row0 + 8) * AST + col0 + 4];
      int bro = (k8 * 8 + acol) * BST + bn;
      #pragma unroll
      for (int nt = 0; nt < 13; nt++) {
        uint32_t b0 = Bsu[bro + nt * 8];
        uint32_t b1 = Bsu[bro + 4 * BST + nt * 8];
        asm volatile(
          "mma.sync.aligned.m16n8k8.row.col.f32.tf32.tf32.f32 "
          "{%0,%1,%2,%3}, {%4,%5,%6,%7}, {%8,%9}, {%0,%1,%2,%3};"
          : "+f"(c[nt][0]), "+f"(c[nt][1]), "+f"(c[nt][2]), "+f"(c[nt][3])
          : "r"(a0), "r"(a1), "r"(a2), "r"(a3), "r"(b0), "r"(b1));
      }
    }
  }
  __syncthreads();

  // epilogue: C fragments -> smem logits Ls[64 px][108]
  float* Ls = smK;                   // reuse (64*108 = 6912 <= 12352)
  {
    int m0 = wid * 16 + (lane >> 2);
    int e0 = 2 * (lane & 3);
    #pragma unroll
    for (int nt = 0; nt < 13; nt++) {
      int e = nt * 8 + e0;
      Ls[m0 * LST + e]           = c[nt][0];
      Ls[m0 * LST + e + 1]       = c[nt][1];
      Ls[(m0 + 8) * LST + e]     = c[nt][2];
      Ls[(m0 + 8) * LST + e + 1] = c[nt][3];
    }
  }
  __syncthreads();

  // softmax: thread = (pixel-pair, ij); 2 pixels each
  int ij = tid & 3;
  int tp = tid >> 2;
  #pragma unroll
  for (int s = 0; s < 2; s++) {
    int m = 2 * tp + s;
    float acc[25];
    #pragma unroll
    for (int k = 0; k < 25; k++)
      acc[k] = Ls[m * LST + 4 * k + ij] + __ldg(b_enc + 4 * k + ij);

    float mx = acc[0];
    #pragma unroll
    for (int k = 1; k < 25; k++) mx = fmaxf(mx, acc[k]);
    float sum = 0.f;
    #pragma unroll
    for (int k = 0; k < 25; k++) { acc[k] = __expf(acc[k] - mx); sum += acc[k]; }
    float inv = 1.0f / sum;

    int pglob = (h0 + (m >> 3)) * W + w0 + (m & 7);
    float* mp = g_mask + (size_t)(n * HW + pglob) * MASK_STRIDE + ij * 28;
    #pragma unroll
    for (int k = 0; k < 25; k++) mp[k] = acc[k] * inv;
  }
}

// ---------------------------------------------------------------------------
// Kernel 3 (v8, unchanged): CARAFE reassembly, channel-pair mainloop.
// ---------------------------------------------------------------------------
#define XS_STRIDE 148

__global__ void __launch_bounds__(256, 3) reassemble_kernel(
    const float* __restrict__ x,
    float* __restrict__ out) {
  __shared__ float ms[64 * MASK_STRIDE];       // 29.7 KB
  __shared__ float xs[2][8 * XS_STRIDE];       // 2 x 4.7 KB

  int tid = threadIdx.x;
  int cg  = tid & 3;
  int pix = tid >> 2;
  int r = pix >> 3, cl = pix & 7;

  int b    = blockIdx.x;          // 1024 blocks
  int cgrp = b & 3;
  int t    = (b >> 2) & 63;
  int n    = b >> 8;
  int h0 = (t >> 3) * 8, w0 = (t & 7) * 8;

  int chl  = tid >> 5;
  int slot = tid & 31;
  int goff[5];
  unsigned lmask = 0, smask = 0;
  #pragma unroll
  for (int q = 0; q < 5; q++) {
    int pos = slot + q * 32;
    int yy = pos / 12, xx = pos - yy * 12;
    int gh = h0 - 2 + yy, gw = w0 - 2 + xx;
    bool in_tile = pos < 144;
    bool v = in_tile && gh >= 0 && gh < H && gw >= 0 && gw < W;
    goff[q] = gh * W + gw;
    if (v) lmask |= (1u << q);
    if (in_tile) smask |= (1u << q);
  }
  int sbase = chl * XS_STRIDE + slot;
  const float* xrow = x + ((size_t)(n * C_IN + cgrp * 64 + chl)) * HW;

  {
    float4* msd = (float4*)ms;
    for (int i = tid; i < 64 * 29; i += 256) {
      int pp  = i / 29;
      int off = i - pp * 29;
      int p = (h0 + (pp >> 3)) * W + w0 + (pp & 7);
      msd[i] = ((const float4*)(g_mask + (size_t)(n * HW + p) * MASK_STRIDE))[off];
    }
  }
  #pragma unroll
  for (int q = 0; q < 5; q++) {
    if (smask >> q & 1) {
      float v = (lmask >> q & 1) ? __ldg(xrow + goff[q]) : 0.f;
      xs[0][sbase + q * 32] = v;
    }
  }
  __syncthreads();

  for (int cc = 0; cc < 8; cc++) {
    if (cc + 1 < 8) {
      const float* xp = xrow + (size_t)(cc + 1) * 8 * HW;
      #pragma unroll
      for (int q = 0; q < 5; q++) {
        if (smask >> q & 1) {
          float v = (lmask >> q & 1) ? __ldg(xp + goff[q]) : 0.f;
          xs[(cc + 1) & 1][sbase + q * 32] = v;
        }
      }
    }

    const float* xbuf = xs[cc & 1];
    int ch0 = cg * 2;

    float xw0[25], xw1[25];
    #pragma unroll
    for (int dy = 0; dy < 5; dy++)
      #pragma unroll
      for (int dx = 0; dx < 5; dx++) {
        int o = (r + dy) * 12 + cl + dx;
        xw0[dy * 5 + dx] = xbuf[ch0 * XS_STRIDE + o];
        xw1[dy * 5 + dx] = xbuf[(ch0 + 1) * XS_STRIDE + o];
      }

    float res0[4], res1[4];
    #pragma unroll
    for (int ij2 = 0; ij2 < 4; ij2++) {
      const float* mb = ms + pix * MASK_STRIDE + ij2 * 28;
      const float4* mb4 = (const float4*)mb;
      float a0 = 0.f, a1 = 0.f;
      #pragma unroll
      for (int q = 0; q < 6; q++) {
        float4 m4 = mb4[q];
        a0 += m4.x * xw0[q*4+0] + m4.y * xw0[q*4+1]
            + m4.z * xw0[q*4+2] + m4.w * xw0[q*4+3];
        a1 += m4.x * xw1[q*4+0] + m4.y * xw1[q*4+1]
            + m4.z * xw1[q*4+2] + m4.w * xw1[q*4+3];
      }
      float ml = mb[24];
      a0 += ml * xw0[24];
      a1 += ml * xw1[24];
      res0[ij2] = a0;  res1[ij2] = a1;
    }

    int c_glob = cgrp * 64 + cc * 8 + ch0;
    float* ob0 = out + ((size_t)(n * C_IN + c_glob) * 128 + 2 * (h0 + r)) * 128
                     + 2 * (w0 + cl);
    float* ob1 = ob0 + 128 * 128;
    ((float2*)ob0)[0]         = make_float2(res0[0], res0[1]);
    ((float2*)(ob0 + 128))[0] = make_float2(res0[2], res0[3]);
    ((float2*)ob1)[0]         = make_float2(res1[0], res1[1]);
    ((float2*)(ob1 + 128))[0] = make_float2(res1[2], res1[3]);

    __syncthreads();
  }
}

// ---------------------------------------------------------------------------
extern "C" void kernel_launch(void* const* d_in, const int* in_sizes, int n_in,
                              void* d_out, int out_size) {
  const float* x      = (const float*)d_in[0];
  const float* w_comp = (const float*)d_in[1];
  const float* b_comp = (const float*)d_in[2];
  const float* w_enc  = (const float*)d_in[3];
  const float* b_enc  = (const float*)d_in[4];
  float* out = (float*)d_out;

  cudaFuncSetAttribute(conv1x1_kernel,
                       cudaFuncAttributeMaxDynamicSharedMemorySize, K1_SMEM);
  cudaFuncSetAttribute(conv3x3_softmax_kernel,
                       cudaFuncAttributeMaxDynamicSharedMemorySize, K2_SMEM);

  build_wB_kernel<<<234, 256>>>(w_enc);
  conv1x1_kernel<<<256, 256, K1_SMEM>>>(x, w_comp, b_comp);
  conv3x3_softmax_kernel<<<256, 128, K2_SMEM>>>(b_enc);
  reassemble_kernel<<<1024, 256>>>(x, out);
}

// round 17
// speedup vs baseline: 1.4316x; 1.1948x over previous
#include <cuda_runtime.h>
#include <cstdint>

// Problem constants
#define N_IMG 4
#define C_IN  256
#define C_MID 64
#define H     64
#define W     64
#define HW    4096
#define KK    25
#define MASK_STRIDE 116

// Scratch (device globals; no allocation allowed)
__device__ float g_comp[N_IMG * C_MID * HW];            // [n][oc][p]
__device__ float g_mask[N_IMG * HW * MASK_STRIDE];      // [n][p][ij*28+k]
__device__ float g_wB[576 * 104];                       // [kk=tap*64+ic][e pad 104], tf32

// ---------------------------------------------------------------------------
// Kernel 0: build B matrix, TAP-MAJOR K ordering (kk = tap*64 + ic).
// ---------------------------------------------------------------------------
__global__ void build_wB_kernel(const float* __restrict__ w_enc) {
  int i = blockIdx.x * 256 + threadIdx.x;      // over 576*104 = 59904
  if (i >= 576 * 104) return;
  int kk = i / 104;
  int e  = i - kk * 104;
  int tap = kk >> 6;
  int ic  = kk & 63;
  float v = (e < 100) ? w_enc[e * 576 + ic * 9 + tap] : 0.f;
  uint32_t tv;
  asm("cvt.rna.tf32.f32 %0, %1;" : "=r"(tv) : "f"(v));
  ((uint32_t*)g_wB)[i] = tv;
}

// ---------------------------------------------------------------------------
// Kernel 1 (v6, unchanged): 1x1 conv 256 -> 64.
// ---------------------------------------------------------------------------
#define WT_STR 36
#define K1_SMEM ((256 * WT_STR + 32 * 128) * 4)   // 53248 B

__global__ void __launch_bounds__(256) conv1x1_kernel(
    const float* __restrict__ x,
    const float* __restrict__ w_comp,
    const float* __restrict__ b_comp) {
  extern __shared__ float sm1[];
  float* wt = sm1;                  // [256][36]
  float* xs = sm1 + 256 * WT_STR;   // [32][128]

  int tid = threadIdx.x;
  int ocg = tid & 3;
  int pp  = tid >> 2;

  int b     = blockIdx.x;          // 256 blocks
  int oc0   = (b & 1) * 32;
  int gp0   = (b >> 1) * 128;
  int n     = gp0 >> 12;
  int pbase = gp0 & 4095;

  for (int i = tid; i < 256 * 32; i += 256) {
    int j = i >> 8;
    int c = i & 255;
    wt[c * WT_STR + j] = w_comp[(oc0 + j) * 256 + c];
  }

  const float* xb = x + (size_t)n * C_IN * HW + pbase;

  float acc[16];
  #pragma unroll
  for (int j = 0; j < 8; j++) {
    float bv = __ldg(b_comp + oc0 + ocg * 8 + j);
    acc[j] = bv; acc[8 + j] = bv;
  }

  for (int cc = 0; cc < 8; cc++) {
    __syncthreads();
    {
      int c   = tid >> 5;
      int px4 = (tid & 31) * 4;
      #pragma unroll
      for (int i2 = 0; i2 < 4; i2++) {
        int ch = c + i2 * 8;
        float4 v = *(const float4*)(xb + (cc * 32 + ch) * HW + px4);
        *(float4*)(xs + ch * 128 + px4) = v;
      }
    }
    __syncthreads();

    #pragma unroll 8
    for (int c = 0; c < 32; c++) {
      float xv0 = xs[c * 128 + 2 * pp];
      float xv1 = xs[c * 128 + 2 * pp + 1];
      const float4* wr =
          (const float4*)(wt + (cc * 32 + c) * WT_STR + ocg * 8);
      float4 w0 = wr[0], w1 = wr[1];
      acc[0]  += w0.x * xv0;  acc[8]  += w0.x * xv1;
      acc[1]  += w0.y * xv0;  acc[9]  += w0.y * xv1;
      acc[2]  += w0.z * xv0;  acc[10] += w0.z * xv1;
      acc[3]  += w0.w * xv0;  acc[11] += w0.w * xv1;
      acc[4]  += w1.x * xv0;  acc[12] += w1.x * xv1;
      acc[5]  += w1.y * xv0;  acc[13] += w1.y * xv1;
      acc[6]  += w1.z * xv0;  acc[14] += w1.z * xv1;
      acc[7]  += w1.w * xv0;  acc[15] += w1.w * xv1;
    }
  }

  float* ob = g_comp + ((size_t)n * C_MID + oc0 + ocg * 8) * HW + pbase + 2 * pp;
  #pragma unroll
  for (int j = 0; j < 8; j++)
    *(float2*)(ob + j * HW) = make_float2(acc[j], acc[8 + j]);
}

// ---------------------------------------------------------------------------
// Kernel 2 (v8 TENSOR): tf32 im2col GEMM + softmax, DOUBLE-BUFFERED chunks.
// Stage chunk kc+1 (LDG->STS) while MMA'ing chunk kc. Tap-major K: index
// math is kk&63 / kk>>6; bounds predicates CSE per tap. A staged as raw
// fp32 bits (HMMA.TF32 truncates low mantissa; no per-element cvt).
// ---------------------------------------------------------------------------
#define AST 76
#define BST 104
#define LST 108
#define KC  72
#define A_FLOATS (64 * AST)                  // 4864
#define B_FLOATS (KC * BST)                  // 7488
#define BUF_FLOATS (A_FLOATS + B_FLOATS)     // 12352
#define K2_SMEM (2 * BUF_FLOATS * 4)         // 98816 B

__global__ void __launch_bounds__(128) conv3x3_softmax_kernel(
    const float* __restrict__ b_enc) {
  extern __shared__ float smK[];

  int tid  = threadIdx.x;
  int lane = tid & 31;
  int wid  = tid >> 5;

  int b  = blockIdx.x;               // 256 blocks
  int n  = b >> 6;
  int t  = b & 63;
  int h0 = (t >> 3) * 8;
  int w0 = (t & 7) * 8;

  float c[13][4];
  #pragma unroll
  for (int nt = 0; nt < 13; nt++)
    #pragma unroll
    for (int q = 0; q < 4; q++) c[nt][q] = 0.f;

  // staging coords: pixel m_st, kk parity kkl0
  int m_st = tid & 63;
  int r_st = m_st >> 3, c_st = m_st & 7;
  int kkl0 = tid >> 6;

  // mma fragment bases
  int row0 = wid * 16 + (lane >> 2);
  int acol = lane & 3;
  int bn   = lane >> 2;

  const uint32_t* gB = (const uint32_t*)g_wB;
  const float* compb = g_comp + ((size_t)(n * C_MID) << 12);

  // ---- stage one chunk into buffer buf ----
  auto stage = [&](int kc, int buf) {
    uint32_t* Asu = (uint32_t*)(smK + buf * BUF_FLOATS);
    float*    Bsf = smK + buf * BUF_FLOATS + A_FLOATS;
    {
      const float4* src = (const float4*)(gB + kc * KC * BST);
      float4* dst = (float4*)Bsf;
      #pragma unroll 2
      for (int i = tid; i < B_FLOATS / 4; i += 128) dst[i] = src[i];
    }
    #pragma unroll
    for (int j = 0; j < 36; j++) {
      int kkl = kkl0 + 2 * j;
      int kk  = kc * KC + kkl;
      int ic  = kk & 63;
      int tap = kk >> 6;
      int ty  = tap / 3;
      int tx  = tap - ty * 3;
      int gh = h0 + r_st - 1 + ty;
      int gw = w0 + c_st - 1 + tx;
      uint32_t v = 0u;
      if ((unsigned)gh < 64u && (unsigned)gw < 64u)
        v = __float_as_uint(compb[((size_t)ic << 12) + (gh << 6) + gw]);
      Asu[m_st * AST + kkl] = v;
    }
  };

  stage(0, 0);

  for (int kc = 0; kc < 8; kc++) {
    __syncthreads();
    if (kc < 7) stage(kc + 1, (kc + 1) & 1);

    const uint32_t* Asu = (const uint32_t*)(smK + (kc & 1) * BUF_FLOATS);
    const uint32_t* Bsu = (const uint32_t*)(smK + (kc & 1) * BUF_FLOATS) + A_FLOATS;
    #pragma unroll
    for (int k8 = 0; k8 < 9; k8++) {
      int col0 = k8 * 8 + acol;
      uint32_t a0 = Asu[row0 * AST + col0];
      uint32_t a1 = Asu[(row0 + 8) * AST + col0];
      uint32_t a2 = Asu[row0 * AST + col0 + 4];
      uint32_t a3 = Asu[(row0 + 8) * AST + col0 + 4];
      int bro = col0 * BST + bn;
      #pragma unroll
      for (int nt = 0; nt < 13; nt++) {
        uint32_t b0 = Bsu[bro + nt * 8];
        uint32_t b1 = Bsu[bro + 4 * BST + nt * 8];
        asm volatile(
          "mma.sync.aligned.m16n8k8.row.col.f32.tf32.tf32.f32 "
          "{%0,%1,%2,%3}, {%4,%5,%6,%7}, {%8,%9}, {%0,%1,%2,%3};"
          : "+f"(c[nt][0]), "+f"(c[nt][1]), "+f"(c[nt][2]), "+f"(c[nt][3])
          : "r"(a0), "r"(a1), "r"(a2), "r"(a3), "r"(b0), "r"(b1));
      }
    }
  }
  __syncthreads();

  // epilogue: C fragments -> smem logits Ls[64 px][108]
  float* Ls = smK;
  {
    int m0 = wid * 16 + (lane >> 2);
    int e0 = 2 * (lane & 3);
    #pragma unroll
    for (int nt = 0; nt < 13; nt++) {
      int e = nt * 8 + e0;
      Ls[m0 * LST + e]           = c[nt][0];
      Ls[m0 * LST + e + 1]       = c[nt][1];
      Ls[(m0 + 8) * LST + e]     = c[nt][2];
      Ls[(m0 + 8) * LST + e + 1] = c[nt][3];
    }
  }
  __syncthreads();

  // softmax: thread = (pixel-pair, ij); 2 pixels each
  int ij = tid & 3;
  int tp = tid >> 2;
  #pragma unroll
  for (int s = 0; s < 2; s++) {
    int m = 2 * tp + s;
    float acc[25];
    #pragma unroll
    for (int k = 0; k < 25; k++)
      acc[k] = Ls[m * LST + 4 * k + ij] + __ldg(b_enc + 4 * k + ij);

    float mx = acc[0];
    #pragma unroll
    for (int k = 1; k < 25; k++) mx = fmaxf(mx, acc[k]);
    float sum = 0.f;
    #pragma unroll
    for (int k = 0; k < 25; k++) { acc[k] = __expf(acc[k] - mx); sum += acc[k]; }
    float inv = 1.0f / sum;

    int pglob = (h0 + (m >> 3)) * W + w0 + (m & 7);
    float* mp = g_mask + (size_t)(n * HW + pglob) * MASK_STRIDE + ij * 28;
    #pragma unroll
    for (int k = 0; k < 25; k++) mp[k] = acc[k] * inv;
  }
}

// ---------------------------------------------------------------------------
// Kernel 3 (v8, unchanged): CARAFE reassembly, channel-pair mainloop.
// ---------------------------------------------------------------------------
#define XS_STRIDE 148

__global__ void __launch_bounds__(256, 3) reassemble_kernel(
    const float* __restrict__ x,
    float* __restrict__ out) {
  __shared__ float ms[64 * MASK_STRIDE];       // 29.7 KB
  __shared__ float xs[2][8 * XS_STRIDE];       // 2 x 4.7 KB

  int tid = threadIdx.x;
  int cg  = tid & 3;
  int pix = tid >> 2;
  int r = pix >> 3, cl = pix & 7;

  int b    = blockIdx.x;          // 1024 blocks
  int cgrp = b & 3;
  int t    = (b >> 2) & 63;
  int n    = b >> 8;
  int h0 = (t >> 3) * 8, w0 = (t & 7) * 8;

  int chl  = tid >> 5;
  int slot = tid & 31;
  int goff[5];
  unsigned lmask = 0, smask = 0;
  #pragma unroll
  for (int q = 0; q < 5; q++) {
    int pos = slot + q * 32;
    int yy = pos / 12, xx = pos - yy * 12;
    int gh = h0 - 2 + yy, gw = w0 - 2 + xx;
    bool in_tile = pos < 144;
    bool v = in_tile && gh >= 0 && gh < H && gw >= 0 && gw < W;
    goff[q] = gh * W + gw;
    if (v) lmask |= (1u << q);
    if (in_tile) smask |= (1u << q);
  }
  int sbase = chl * XS_STRIDE + slot;
  const float* xrow = x + ((size_t)(n * C_IN + cgrp * 64 + chl)) * HW;

  {
    float4* msd = (float4*)ms;
    for (int i = tid; i < 64 * 29; i += 256) {
      int pp  = i / 29;
      int off = i - pp * 29;
      int p = (h0 + (pp >> 3)) * W + w0 + (pp & 7);
      msd[i] = ((const float4*)(g_mask + (size_t)(n * HW + p) * MASK_STRIDE))[off];
    }
  }
  #pragma unroll
  for (int q = 0; q < 5; q++) {
    if (smask >> q & 1) {
      float v = (lmask >> q & 1) ? __ldg(xrow + goff[q]) : 0.f;
      xs[0][sbase + q * 32] = v;
    }
  }
  __syncthreads();

  for (int cc = 0; cc < 8; cc++) {
    if (cc + 1 < 8) {
      const float* xp = xrow + (size_t)(cc + 1) * 8 * HW;
      #pragma unroll
      for (int q = 0; q < 5; q++) {
        if (smask >> q & 1) {
          float v = (lmask >> q & 1) ? __ldg(xp + goff[q]) : 0.f;
          xs[(cc + 1) & 1][sbase + q * 32] = v;
        }
      }
    }

    const float* xbuf = xs[cc & 1];
    int ch0 = cg * 2;

    float xw0[25], xw1[25];
    #pragma unroll
    for (int dy = 0; dy < 5; dy++)
      #pragma unroll
      for (int dx = 0; dx < 5; dx++) {
        int o = (r + dy) * 12 + cl + dx;
        xw0[dy * 5 + dx] = xbuf[ch0 * XS_STRIDE + o];
        xw1[dy * 5 + dx] = xbuf[(ch0 + 1) * XS_STRIDE + o];
      }

    float res0[4], res1[4];
    #pragma unroll
    for (int ij2 = 0; ij2 < 4; ij2++) {
      const float* mb = ms + pix * MASK_STRIDE + ij2 * 28;
      const float4* mb4 = (const float4*)mb;
      float a0 = 0.f, a1 = 0.f;
      #pragma unroll
      for (int q = 0; q < 6; q++) {
        float4 m4 = mb4[q];
        a0 += m4.x * xw0[q*4+0] + m4.y * xw0[q*4+1]
            + m4.z * xw0[q*4+2] + m4.w * xw0[q*4+3];
        a1 += m4.x * xw1[q*4+0] + m4.y * xw1[q*4+1]
            + m4.z * xw1[q*4+2] + m4.w * xw1[q*4+3];
      }
      float ml = mb[24];
      a0 += ml * xw0[24];
      a1 += ml * xw1[24];
      res0[ij2] = a0;  res1[ij2] = a1;
    }

    int c_glob = cgrp * 64 + cc * 8 + ch0;
    float* ob0 = out + ((size_t)(n * C_IN + c_glob) * 128 + 2 * (h0 + r)) * 128
                     + 2 * (w0 + cl);
    float* ob1 = ob0 + 128 * 128;
    ((float2*)ob0)[0]         = make_float2(res0[0], res0[1]);
    ((float2*)(ob0 + 128))[0] = make_float2(res0[2], res0[3]);
    ((float2*)ob1)[0]         = make_float2(res1[0], res1[1]);
    ((float2*)(ob1 + 128))[0] = make_float2(res1[2], res1[3]);

    __syncthreads();
  }
}

// ---------------------------------------------------------------------------
extern "C" void kernel_launch(void* const* d_in, const int* in_sizes, int n_in,
                              void* d_out, int out_size) {
  const float* x      = (const float*)d_in[0];
  const float* w_comp = (const float*)d_in[1];
  const float* b_comp = (const float*)d_in[2];
  const float* w_enc  = (const float*)d_in[3];
  const float* b_enc  = (const float*)d_in[4];
  float* out = (float*)d_out;

  cudaFuncSetAttribute(conv1x1_kernel,
                       cudaFuncAttributeMaxDynamicSharedMemorySize, K1_SMEM);
  cudaFuncSetAttribute(conv3x3_softmax_kernel,
                       cudaFuncAttributeMaxDynamicSharedMemorySize, K2_SMEM);

  build_wB_kernel<<<234, 256>>>(w_enc);
  conv1x1_kernel<<<256, 256, K1_SMEM>>>(x, w_comp, b_comp);
  conv3x3_softmax_kernel<<<256, 128, K2_SMEM>>>(b_enc);
  reassemble_kernel<<<1024, 256>>>(x, out);
}